// round 3
// baseline (speedup 1.0000x reference)
#include <cuda_runtime.h>
#include <cuda_bf16.h>
#include <cstdint>

#define D_MODEL 2048
#define N_HEADS 16
#define D_FF    8192
#define BB      4
#define TT      1024
#define BT      (BB*TT)      // 4096 tokens
#define DH      128
#define BH      (BB*N_HEADS) // 64

// ---------------- scratch (device globals; no allocs allowed) ----------------
__device__ float g_xh [(long)BT*D_MODEL];
__device__ float g_q  [(long)BT*D_MODEL];   // [b,h,t,d]
__device__ float g_k  [(long)BT*D_MODEL];   // [b,h,t,d]
__device__ float g_vt [(long)BT*D_MODEL];   // [b,h,d,t]  (transposed V)
__device__ float g_sc [(long)BH*TT*TT];     // scores / probs (in-place)
__device__ float g_at [(long)BT*D_MODEL];   // attention output [b,t,h*d]
__device__ float g_ah [(long)BT*D_MODEL];   // hadamard(attn out)
__device__ float g_x1 [(long)BT*D_MODEL];   // residual after O proj
__device__ float g_xh2[(long)BT*D_MODEL];
__device__ float g_ff [(long)BT*D_FF];
__device__ float g_ffh[(long)BT*D_FF];

// canonical int8 weights (harness may deliver int8 promoted to int32/float32)
__device__ int8_t g_w[(long)4*D_MODEL*D_MODEL + (long)2*D_FF*D_MODEL];
__device__ int g_cnt32;
__device__ int g_cntf;

// ---------------- dtype probe + weight normalization ----------------
__global__ void zero_counters() { g_cnt32 = 0; g_cntf = 0; }

__global__ void probe_dtype(const void* __restrict__ p, int nwords)
{
    int i = blockIdx.x * blockDim.x + threadIdx.x;
    if (i >= nwords) return;
    int v = ((const int*)p)[i];
    if (v < -127 || v > 127) atomicAdd(&g_cnt32, 1);
    float f = ((const float*)p)[i];
    bool okf = (f >= -127.0f) && (f <= 127.0f) && (f == rintf(f));
    if (!okf) atomicAdd(&g_cntf, 1);
}

__global__ void convert_w(const void* __restrict__ src, int8_t* __restrict__ dst, long n)
{
    long i = (long)blockIdx.x * blockDim.x + threadIdx.x;
    if (i >= n) return;
    int mode = (g_cnt32 == 0) ? 1 : ((g_cntf == 0) ? 2 : 0);  // 1=int32, 2=float32, 0=int8
    int8_t v;
    if (mode == 1)      v = (int8_t)((const int*)src)[i];
    else if (mode == 2) v = (int8_t)__float2int_rn(((const float*)src)[i]);
    else                v = ((const int8_t*)src)[i];
    dst[i] = v;
}

// ---------------- mma helper ----------------
__device__ __forceinline__ void mma16816(float* c, uint32_t a0, uint32_t a1, uint32_t a2, uint32_t a3,
                                         uint32_t b0, uint32_t b1) {
    asm volatile("mma.sync.aligned.m16n8k16.row.col.f32.bf16.bf16.f32 "
                 "{%0,%1,%2,%3},{%4,%5,%6,%7},{%8,%9},{%0,%1,%2,%3};"
                 : "+f"(c[0]), "+f"(c[1]), "+f"(c[2]), "+f"(c[3])
                 : "r"(a0), "r"(a1), "r"(a2), "r"(a3), "r"(b0), "r"(b1));
}

// ============================================================================
// GEMM-W: C[M,N] = (A_f32[M,K] @ W_int8[N,K]^T) * s[N]  (+bias) (+res)
// fp32 emulated via bf16 hi/lo split of A (double-K), W exact in bf16.
// Block 128x128, 8 warps (2M x 4N), warp tile 64x32, BK(real)=32.
// LAYOUT: 0 = out[r*ldc+c], 1 = q/k head layout, 2 = transposed-V layout
// ============================================================================
template<int LAYOUT, bool HAS_BIAS, bool HAS_RES>
__global__ void __launch_bounds__(256) gemm_w(
    const float* __restrict__ A, int K, const int8_t* __restrict__ W,
    const float* __restrict__ s, const float* __restrict__ bias,
    const float* __restrict__ res, float* __restrict__ out, int ldc)
{
    constexpr int ST = 72; // padded bf16 row stride (conflict-free frag reads)
    __shared__ __align__(16) __nv_bfloat16 sA[128 * ST];
    __shared__ __align__(16) __nv_bfloat16 sB[128 * ST];

    const int tid = threadIdx.x, lane = tid & 31, w = tid >> 5;
    const int wm = w & 1, wn = w >> 1;           // warp grid 2(M) x 4(N)
    const int m0 = blockIdx.y * 128, n0 = blockIdx.x * 128;
    const int tg = lane >> 2, tk = (lane & 3) * 2;  // fragment coords

    float acc[4][4][4];
    #pragma unroll
    for (int i = 0; i < 4; i++)
        #pragma unroll
        for (int j = 0; j < 4; j++)
            #pragma unroll
            for (int e = 0; e < 4; e++) acc[i][j][e] = 0.f;

    const int la_k = tid & 31, la_r = tid >> 5;  // A loader: 32 k-lanes x 8 rows
    const int lb_n = tid >> 3, lb_k4 = tid & 7;  // B loader: char4, 8 k4-lanes x 32 n

    for (int kb = 0; kb < K; kb += 32) {
        // --- load A tile, split into hi/lo interleaved (kk = 2k, 2k+1) ---
        const float* Ap = A + (long)m0 * K + kb;
        #pragma unroll
        for (int it = 0; it < 16; it++) {
            int r = la_r + it * 8;
            float v = Ap[(long)r * K + la_k];
            __nv_bfloat16 hi = __float2bfloat16(v);
            __nv_bfloat16 lo = __float2bfloat16(v - __bfloat162float(hi));
            sA[r * ST + 2 * la_k]     = hi;
            sA[r * ST + 2 * la_k + 1] = lo;
        }
        // --- load W tile int8 -> bf16 (exact), duplicated into both kk slots ---
        #pragma unroll
        for (int it = 0; it < 4; it++) {
            int n = lb_n + it * 32;
            char4 c4 = *(const char4*)(W + (long)(n0 + n) * K + kb + 4 * lb_k4);
            int kk0 = 4 * lb_k4;
            signed char vs[4] = {c4.x, c4.y, c4.z, c4.w};
            #pragma unroll
            for (int bv = 0; bv < 4; bv++) {
                __nv_bfloat16 wv = __float2bfloat16((float)vs[bv]);
                sB[n * ST + 2 * (kk0 + bv)]     = wv;
                sB[n * ST + 2 * (kk0 + bv) + 1] = wv;
            }
        }
        __syncthreads();
        // --- 4 k16 steps over KK=64 ---
        #pragma unroll
        for (int ks = 0; ks < 4; ks++) {
            const int kk0 = ks * 16;
            uint32_t af[4][4], bf[4][2];
            #pragma unroll
            for (int i = 0; i < 4; i++) {
                int ra = wm * 64 + i * 16 + tg;
                af[i][0] = *(const uint32_t*)&sA[(ra    ) * ST + kk0 + tk    ];
                af[i][1] = *(const uint32_t*)&sA[(ra + 8) * ST + kk0 + tk    ];
                af[i][2] = *(const uint32_t*)&sA[(ra    ) * ST + kk0 + tk + 8];
                af[i][3] = *(const uint32_t*)&sA[(ra + 8) * ST + kk0 + tk + 8];
            }
            #pragma unroll
            for (int j = 0; j < 4; j++) {
                int rb = wn * 32 + j * 8 + tg;
                bf[j][0] = *(const uint32_t*)&sB[rb * ST + kk0 + tk    ];
                bf[j][1] = *(const uint32_t*)&sB[rb * ST + kk0 + tk + 8];
            }
            #pragma unroll
            for (int i = 0; i < 4; i++)
                #pragma unroll
                for (int j = 0; j < 4; j++)
                    mma16816(acc[i][j], af[i][0], af[i][1], af[i][2], af[i][3], bf[j][0], bf[j][1]);
        }
        __syncthreads();
    }

    // --- epilogue ---
    const int gr = tg, gc = tk;
    #pragma unroll
    for (int i = 0; i < 4; i++) {
        #pragma unroll
        for (int j = 0; j < 4; j++) {
            int rbase = m0 + wm * 64 + i * 16 + gr;
            int cbase = n0 + wn * 32 + j * 8 + gc;
            #pragma unroll
            for (int e = 0; e < 4; e++) {
                int r = rbase + (e >> 1) * 8;
                int c = cbase + (e & 1);
                float v = acc[i][j][e] * s[c];
                if (HAS_BIAS) v += bias[c];
                if (HAS_RES)  v += res[(long)r * D_MODEL + c];
                long idx;
                if (LAYOUT == 0) {
                    idx = (long)r * ldc + c;
                } else {
                    int b = r >> 10, t = r & 1023, h = c >> 7, d = c & 127;
                    if (LAYOUT == 1) idx = (long)(b * N_HEADS + h) * (TT * DH) + (long)t * DH + d;
                    else             idx = (long)(b * N_HEADS + h) * (TT * DH) + (long)d * TT + t;
                }
                out[idx] = v;
            }
        }
    }
}

// ============================================================================
// GEMM-P: C[M,N] = A_f32[M,K] @ B_f32[N,K]^T   (both split, triple-K:
//   kk=3k: A_hi*B_hi, kk=3k+1: A_lo*B_hi, kk=3k+2: A_hi*B_lo)
// EPI: 0 = scores (scale 1/sqrt(128)),  1 = P@V (scatter to [b,t,h*128+d])
// ============================================================================
template<int EPI>
__global__ void __launch_bounds__(256) gemm_p(
    const float* __restrict__ Ab, const float* __restrict__ Bb,
    float* __restrict__ outb, int K, int lda, int ldb, long sAz, long sBz)
{
    constexpr int ST = 56; // padded stride
    __shared__ __align__(16) __nv_bfloat16 sA[128 * ST];
    __shared__ __align__(16) __nv_bfloat16 sB[128 * ST];

    const int z = blockIdx.z;
    const float* A = Ab + (long)z * sAz;
    const float* B = Bb + (long)z * sBz;

    const int tid = threadIdx.x, lane = tid & 31, w = tid >> 5;
    const int wm = w & 1, wn = w >> 1;
    const int m0 = blockIdx.y * 128, n0 = blockIdx.x * 128;
    const int tg = lane >> 2, tk = (lane & 3) * 2;

    float acc[4][4][4];
    #pragma unroll
    for (int i = 0; i < 4; i++)
        #pragma unroll
        for (int j = 0; j < 4; j++)
            #pragma unroll
            for (int e = 0; e < 4; e++) acc[i][j][e] = 0.f;

    const int la_k = tid & 15, la_r = tid >> 4;  // 16 k-lanes x 16 rows

    for (int kb = 0; kb < K; kb += 16) {
        #pragma unroll
        for (int it = 0; it < 8; it++) {
            int r = la_r + it * 16;
            float va = A[(long)(m0 + r) * lda + kb + la_k];
            __nv_bfloat16 hi = __float2bfloat16(va);
            __nv_bfloat16 lo = __float2bfloat16(va - __bfloat162float(hi));
            sA[r * ST + 3 * la_k]     = hi;
            sA[r * ST + 3 * la_k + 1] = lo;
            sA[r * ST + 3 * la_k + 2] = hi;
            float vb = B[(long)(n0 + r) * ldb + kb + la_k];
            hi = __float2bfloat16(vb);
            lo = __float2bfloat16(vb - __bfloat162float(hi));
            sB[r * ST + 3 * la_k]     = hi;
            sB[r * ST + 3 * la_k + 1] = hi;
            sB[r * ST + 3 * la_k + 2] = lo;
        }
        __syncthreads();
        #pragma unroll
        for (int ks = 0; ks < 3; ks++) {
            const int kk0 = ks * 16;
            uint32_t af[4][4], bf[4][2];
            #pragma unroll
            for (int i = 0; i < 4; i++) {
                int ra = wm * 64 + i * 16 + tg;
                af[i][0] = *(const uint32_t*)&sA[(ra    ) * ST + kk0 + tk    ];
                af[i][1] = *(const uint32_t*)&sA[(ra + 8) * ST + kk0 + tk    ];
                af[i][2] = *(const uint32_t*)&sA[(ra    ) * ST + kk0 + tk + 8];
                af[i][3] = *(const uint32_t*)&sA[(ra + 8) * ST + kk0 + tk + 8];
            }
            #pragma unroll
            for (int j = 0; j < 4; j++) {
                int rb = wn * 32 + j * 8 + tg;
                bf[j][0] = *(const uint32_t*)&sB[rb * ST + kk0 + tk    ];
                bf[j][1] = *(const uint32_t*)&sB[rb * ST + kk0 + tk + 8];
            }
            #pragma unroll
            for (int i = 0; i < 4; i++)
                #pragma unroll
                for (int j = 0; j < 4; j++)
                    mma16816(acc[i][j], af[i][0], af[i][1], af[i][2], af[i][3], bf[j][0], bf[j][1]);
        }
        __syncthreads();
    }

    const int gr = tg, gc = tk;
    #pragma unroll
    for (int i = 0; i < 4; i++) {
        #pragma unroll
        for (int j = 0; j < 4; j++) {
            int rbase = m0 + wm * 64 + i * 16 + gr;
            int cbase = n0 + wn * 32 + j * 8 + gc;
            #pragma unroll
            for (int e = 0; e < 4; e++) {
                int r = rbase + (e >> 1) * 8;
                int c = cbase + (e & 1);
                float v = acc[i][j][e];
                if (EPI == 0) {
                    outb[(long)z * TT * TT + (long)r * TT + c] = v * 0.08838834764831845f;
                } else {
                    int b = z >> 4, h = z & 15;
                    outb[((long)(b * TT + r)) * D_MODEL + h * DH + c] = v;
                }
            }
        }
    }
}

// ---------------- reductions ----------------
__device__ __forceinline__ float warp_sum(float v) {
    #pragma unroll
    for (int o = 16; o; o >>= 1) v += __shfl_xor_sync(0xffffffffu, v, o);
    return v;
}
__device__ __forceinline__ float warp_max(float v) {
    #pragma unroll
    for (int o = 16; o; o >>= 1) v = fmaxf(v, __shfl_xor_sync(0xffffffffu, v, o));
    return v;
}
template<int NW>
__device__ __forceinline__ float block_sum(float v, float* buf) {
    int tid = threadIdx.x;
    v = warp_sum(v);
    __syncthreads();
    if ((tid & 31) == 0) buf[tid >> 5] = v;
    __syncthreads();
    if (tid == 0) { float t = 0; for (int i = 0; i < NW; i++) t += buf[i]; buf[0] = t; }
    __syncthreads();
    return buf[0];
}
template<int NW>
__device__ __forceinline__ float block_max(float v, float* buf) {
    int tid = threadIdx.x;
    v = warp_max(v);
    __syncthreads();
    if ((tid & 31) == 0) buf[tid >> 5] = v;
    __syncthreads();
    if (tid == 0) { float t = buf[0]; for (int i = 1; i < NW; i++) t = fmaxf(t, buf[i]); buf[0] = t; }
    __syncthreads();
    return buf[0];
}

// ---------------- LN (optional) + Hadamard-2048, one block per token ----------------
template<bool DO_LN>
__global__ void __launch_bounds__(256) ln_had2048(
    const float* __restrict__ in, const float* __restrict__ g,
    const float* __restrict__ bta, float* __restrict__ out)
{
    __shared__ float s[2048];
    __shared__ float red[8];
    const int tid = threadIdx.x;
    const float* x = in + (long)blockIdx.x * 2048;
    float loc[8];
    #pragma unroll
    for (int j = 0; j < 8; j++) loc[j] = x[tid + 256 * j];

    if (DO_LN) {
        float sm = 0.f, sq = 0.f;
        #pragma unroll
        for (int j = 0; j < 8; j++) { sm += loc[j]; sq += loc[j] * loc[j]; }
        float S  = block_sum<8>(sm, red);
        float SQ = block_sum<8>(sq, red);
        float mu = S * (1.0f / 2048.0f);
        float var = SQ * (1.0f / 2048.0f) - mu * mu;
        float inv = rsqrtf(var + 1e-5f);
        #pragma unroll
        for (int j = 0; j < 8; j++) {
            int c = tid + 256 * j;
            loc[j] = (loc[j] - mu) * inv * g[c] + bta[c];
        }
    }
    #pragma unroll
    for (int j = 0; j < 8; j++) s[tid + 256 * j] = loc[j];

    int sh = 0;
    for (int h = 1; h < 2048; h <<= 1, sh++) {
        __syncthreads();
        #pragma unroll
        for (int j = 0; j < 4; j++) {
            int pi = tid + 256 * j;               // 1024 pairs
            int idx = ((pi >> sh) << (sh + 1)) + (pi & (h - 1));
            float a = s[idx], c = s[idx + h];
            s[idx] = a + c;
            s[idx + h] = a - c;
        }
    }
    __syncthreads();
    float* o = out + (long)blockIdx.x * 2048;
    #pragma unroll
    for (int j = 0; j < 8; j++) o[tid + 256 * j] = s[tid + 256 * j] * 0.022097086912079608f;
}

// ---------------- GELU(exact) + Hadamard-8192, one block per token ----------------
__global__ void __launch_bounds__(512) gelu_had8192(const float* __restrict__ in, float* __restrict__ out)
{
    __shared__ float s[8192];
    const int tid = threadIdx.x;
    const float* x = in + (long)blockIdx.x * 8192;
    #pragma unroll
    for (int j = 0; j < 16; j++) {
        float v = x[tid + 512 * j];
        v = 0.5f * v * (1.0f + erff(v * 0.7071067811865476f));
        s[tid + 512 * j] = v;
    }
    int sh = 0;
    for (int h = 1; h < 8192; h <<= 1, sh++) {
        __syncthreads();
        #pragma unroll
        for (int j = 0; j < 8; j++) {
            int pi = tid + 512 * j;               // 4096 pairs
            int idx = ((pi >> sh) << (sh + 1)) + (pi & (h - 1));
            float a = s[idx], c = s[idx + h];
            s[idx] = a + c;
            s[idx + h] = a - c;
        }
    }
    __syncthreads();
    float* o = out + (long)blockIdx.x * 8192;
    #pragma unroll
    for (int j = 0; j < 16; j++) o[tid + 512 * j] = s[tid + 512 * j] * 0.011048543456039806f;
}

// ---------------- softmax over rows of 1024 (in-place), one block per row ----------------
__global__ void __launch_bounds__(256) softmax1024(float* __restrict__ sc)
{
    __shared__ float red[8];
    const int tid = threadIdx.x;
    float* row = sc + (long)blockIdx.x * 1024;
    float v[4];
    float mx = -3.4e38f;
    #pragma unroll
    for (int j = 0; j < 4; j++) { v[j] = row[tid + 256 * j]; mx = fmaxf(mx, v[j]); }
    float m = block_max<8>(mx, red);
    float sm = 0.f;
    #pragma unroll
    for (int j = 0; j < 4; j++) { v[j] = __expf(v[j] - m); sm += v[j]; }
    float S = block_sum<8>(sm, red);
    float inv = 1.0f / S;
    #pragma unroll
    for (int j = 0; j < 4; j++) row[tid + 256 * j] = v[j] * inv;
}

// ============================================================================
extern "C" void kernel_launch(void* const* d_in, const int* in_sizes, int n_in,
                              void* d_out, int out_size)
{
    const float*  x    = (const float*) d_in[0];
    const float*  ln1g = (const float*) d_in[1];
    const float*  ln1b = (const float*) d_in[2];
    const float*  ln2g = (const float*) d_in[3];
    const float*  ln2b = (const float*) d_in[4];
    const void*   Qq   = d_in[5];
    const float*  sq   = (const float*) d_in[6];
    const void*   Qk   = d_in[7];
    const float*  sk   = (const float*) d_in[8];
    const void*   Qv   = d_in[9];
    const float*  sv   = (const float*) d_in[10];
    const void*   Qo   = d_in[11];
    const float*  so   = (const float*) d_in[12];
    const void*   Qf1  = d_in[13];
    const float*  sf1  = (const float*) d_in[14];
    const float*  bf1  = (const float*) d_in[15];
    const void*   Qf2  = d_in[16];
    const float*  sf2  = (const float*) d_in[17];
    const float*  bf2  = (const float*) d_in[18];
    float* out = (float*)d_out;

    float *xh, *q, *k, *vt, *sc, *at, *ah, *x1, *xh2, *ff, *ffh;
    int8_t* wbase;
    cudaGetSymbolAddress((void**)&xh,  g_xh);
    cudaGetSymbolAddress((void**)&q,   g_q);
    cudaGetSymbolAddress((void**)&k,   g_k);
    cudaGetSymbolAddress((void**)&vt,  g_vt);
    cudaGetSymbolAddress((void**)&sc,  g_sc);
    cudaGetSymbolAddress((void**)&at,  g_at);
    cudaGetSymbolAddress((void**)&ah,  g_ah);
    cudaGetSymbolAddress((void**)&x1,  g_x1);
    cudaGetSymbolAddress((void**)&xh2, g_xh2);
    cudaGetSymbolAddress((void**)&ff,  g_ff);
    cudaGetSymbolAddress((void**)&ffh, g_ffh);
    cudaGetSymbolAddress((void**)&wbase, g_w);

    const long NW_D = (long)D_MODEL * D_MODEL;   // 4,194,304
    const long NW_F = (long)D_FF * D_MODEL;      // 16,777,216
    int8_t* wq  = wbase;
    int8_t* wk  = wbase + NW_D;
    int8_t* wv  = wbase + 2 * NW_D;
    int8_t* wo  = wbase + 3 * NW_D;
    int8_t* wf1 = wbase + 4 * NW_D;
    int8_t* wf2 = wbase + 4 * NW_D + NW_F;

    // 0. detect weight dtype (int8 vs harness-promoted int32/float32), normalize to int8
    zero_counters<<<1, 1>>>();
    probe_dtype<<<4096, 256>>>(Qq, 1 << 20);   // first 1M words (4MB: safe for all dtypes)
    convert_w<<<(int)((NW_D + 255) / 256), 256>>>(Qq,  wq,  NW_D);
    convert_w<<<(int)((NW_D + 255) / 256), 256>>>(Qk,  wk,  NW_D);
    convert_w<<<(int)((NW_D + 255) / 256), 256>>>(Qv,  wv,  NW_D);
    convert_w<<<(int)((NW_D + 255) / 256), 256>>>(Qo,  wo,  NW_D);
    convert_w<<<(int)((NW_F + 255) / 256), 256>>>(Qf1, wf1, NW_F);
    convert_w<<<(int)((NW_F + 255) / 256), 256>>>(Qf2, wf2, NW_F);

    // 1. LN1 + Hadamard
    ln_had2048<true><<<BT, 256>>>(x, ln1g, ln1b, xh);
    // 2-4. Q/K/V projections (int8 weights, per-row scale)
    gemm_w<1, false, false><<<dim3(16, 32), 256>>>(xh, D_MODEL, wq, sq, nullptr, nullptr, q,  D_MODEL);
    gemm_w<1, false, false><<<dim3(16, 32), 256>>>(xh, D_MODEL, wk, sk, nullptr, nullptr, k,  D_MODEL);
    gemm_w<2, false, false><<<dim3(16, 32), 256>>>(xh, D_MODEL, wv, sv, nullptr, nullptr, vt, D_MODEL);
    // 5. scores = q @ k^T / sqrt(128)   per (b,h)
    gemm_p<0><<<dim3(8, 8, BH), 256>>>(q, k, sc, DH, DH, DH, (long)TT * DH, (long)TT * DH);
    // 6. softmax
    softmax1024<<<BH * TT, 256>>>(sc);
    // 7. attn = P @ V   (V stored transposed [d][t])
    gemm_p<1><<<dim3(1, 8, BH), 256>>>(sc, vt, at, TT, TT, TT, (long)TT * TT, (long)DH * TT);
    // 8. Hadamard(attn)
    ln_had2048<false><<<BT, 256>>>(at, nullptr, nullptr, ah);
    // 9. x1 = x + O-proj
    gemm_w<0, false, true><<<dim3(16, 32), 256>>>(ah, D_MODEL, wo, so, nullptr, x, x1, D_MODEL);
    // 10. LN2 + Hadamard
    ln_had2048<true><<<BT, 256>>>(x1, ln2g, ln2b, xh2);
    // 11. FF1 (+bias)
    gemm_w<0, true, false><<<dim3(64, 32), 256>>>(xh2, D_MODEL, wf1, sf1, bf1, nullptr, ff, D_FF);
    // 12. GELU + Hadamard-8192
    gelu_had8192<<<BT, 512>>>(ff, ffh);
    // 13. out = x1 + FF2 (+bias)
    gemm_w<0, true, true><<<dim3(16, 32), 256>>>(ffh, D_FF, wf2, sf2, bf2, x1, out, D_MODEL);
}

// round 5
// speedup vs baseline: 1.2965x; 1.2965x over previous
#include <cuda_runtime.h>
#include <cuda_bf16.h>
#include <cstdint>

#define D_MODEL 2048
#define N_HEADS 16
#define D_FF    8192
#define BB      4
#define TT      1024
#define BT      (BB*TT)      // 4096 tokens
#define DH      128
#define BH      (BB*N_HEADS) // 64

// ---------------- scratch (device globals; no allocs allowed) ----------------
__device__ float g_q  [(long)BT*D_MODEL];   // [b,h,t,d]
__device__ float g_k  [(long)BT*D_MODEL];   // [b,h,t,d]
__device__ float g_vt [(long)BT*D_MODEL];   // [b,h,d,t]  (transposed V)
__device__ float g_sc [(long)BH*TT*TT];     // scores / probs (in-place)
__device__ float g_at [(long)BT*D_MODEL];   // attention output [b,t,h*d]
__device__ float g_x1 [(long)BT*D_MODEL];   // residual after O proj
__device__ float g_ff [(long)BT*D_FF];

// hi/lo split activations (bf16 interleaved: kk=2c hi, 2c+1 lo)
__device__ __nv_bfloat16 g_xhs [(long)BT*2*D_MODEL];
__device__ __nv_bfloat16 g_ahs [(long)BT*2*D_MODEL];
__device__ __nv_bfloat16 g_xh2s[(long)BT*2*D_MODEL];
__device__ __nv_bfloat16 g_ffhs[(long)BT*2*D_FF];

// K-duplicated bf16 weights: w[n][2k] = w[n][2k+1] = W[n][k]
#define NWD2 ((long)D_MODEL*2*D_MODEL)   // 8,388,608
#define NWF2 ((long)D_FF*2*D_MODEL)      // 33,554,432
__device__ __nv_bfloat16 g_wb[(long)4*NWD2 + 2*NWF2];
__device__ int g_cnt32;
__device__ int g_cntf;

// ---------------- dtype probe + weight normalization ----------------
__global__ void zero_counters() { g_cnt32 = 0; g_cntf = 0; }

__global__ void probe_dtype(const void* __restrict__ p, int nwords)
{
    int i = blockIdx.x * blockDim.x + threadIdx.x;
    if (i >= nwords) return;
    int v = ((const int*)p)[i];
    if (v < -127 || v > 127) atomicAdd(&g_cnt32, 1);
    float f = ((const float*)p)[i];
    bool okf = (f >= -127.0f) && (f <= 127.0f) && (f == rintf(f));
    if (!okf) atomicAdd(&g_cntf, 1);
}

// src weight i -> dst pair (2i, 2i+1), both = bf16(w)
__global__ void convert_w(const void* __restrict__ src, __nv_bfloat16* __restrict__ dst, long n)
{
    long i = (long)blockIdx.x * blockDim.x + threadIdx.x;
    if (i >= n) return;
    int mode = (g_cnt32 == 0) ? 1 : ((g_cntf == 0) ? 2 : 0);  // 1=int32, 2=float32, 0=int8
    signed char v;
    if (mode == 1)      v = (signed char)((const int*)src)[i];
    else if (mode == 2) v = (signed char)__float2int_rn(((const float*)src)[i]);
    else                v = ((const signed char*)src)[i];
    __nv_bfloat16 b = __float2bfloat16((float)v);
    ((__nv_bfloat162*)dst)[i] = __halves2bfloat162(b, b);
}

// ---------------- mma / ldmatrix / cp.async helpers ----------------
__device__ __forceinline__ void ldsm_x4(uint32_t& r0, uint32_t& r1, uint32_t& r2, uint32_t& r3, uint32_t a) {
    asm volatile("ldmatrix.sync.aligned.m8n8.x4.shared.b16 {%0,%1,%2,%3},[%4];"
                 : "=r"(r0), "=r"(r1), "=r"(r2), "=r"(r3) : "r"(a));
}
__device__ __forceinline__ void ldsm_x2(uint32_t& r0, uint32_t& r1, uint32_t a) {
    asm volatile("ldmatrix.sync.aligned.m8n8.x2.shared.b16 {%0,%1},[%2];"
                 : "=r"(r0), "=r"(r1) : "r"(a));
}
__device__ __forceinline__ void mma16816(float* c, uint32_t a0, uint32_t a1, uint32_t a2, uint32_t a3,
                                         uint32_t b0, uint32_t b1) {
    asm volatile("mma.sync.aligned.m16n8k16.row.col.f32.bf16.bf16.f32 "
                 "{%0,%1,%2,%3},{%4,%5,%6,%7},{%8,%9},{%0,%1,%2,%3};"
                 : "+f"(c[0]), "+f"(c[1]), "+f"(c[2]), "+f"(c[3])
                 : "r"(a0), "r"(a1), "r"(a2), "r"(a3), "r"(b0), "r"(b1));
}
__device__ __forceinline__ void cp16(uint32_t dst, const void* src) {
    asm volatile("cp.async.cg.shared.global [%0], [%1], 16;"
                 :: "r"(dst), "l"(__cvta_generic_to_global(src)) : "memory");
}
__device__ __forceinline__ uint32_t smem_u32(const void* p) {
    uint32_t a;
    asm("{ .reg .u64 t; cvta.to.shared.u64 t, %1; cvt.u32.u64 %0, t; }" : "=r"(a) : "l"(p));
    return a;
}

// ============================================================================
// GEMM-W v2 (pure bf16, cp.async 3-stage pipeline):
//   C[M=4096, N] = A2[M, K2] @ W2[N, K2]^T  then *s[col] (+bias) (+res)
// A2 = hi/lo-split activations, W2 = K-duplicated weights (both bf16).
// CTA tile 128x128, kk-block 64. 8 warps (2M x 4N), warp tile 64x32.
// Smem: per stage A 128x64 bf16 (128B rows, chunk-XOR swizzle), B same.
// LAYOUT: 0 = out[r*ldc+c], 1 = q/k head layout, 2 = transposed-V layout
// ============================================================================
#define WST 32768                     // bytes per stage (A 16K + B 16K)
#define SM_A(s) ((s)*WST)
#define SM_B(s) ((s)*WST + 16384)
#define SMEM_W  (3*WST)               // 98304 bytes

template<int LAYOUT, bool HAS_BIAS, bool HAS_RES>
__global__ void __launch_bounds__(256) gemm_w2(
    const __nv_bfloat16* __restrict__ A, const __nv_bfloat16* __restrict__ W, int K2,
    const float* __restrict__ s, const float* __restrict__ bias,
    const float* __restrict__ res, float* __restrict__ out, int ldc)
{
    extern __shared__ char smem[];
    const uint32_t sb = smem_u32(smem);
    const int tid = threadIdx.x, lane = tid & 31, w = tid >> 5;
    const int wm = w & 1, wn = w >> 1;           // warp grid 2(M) x 4(N)
    const int m0 = blockIdx.y * 128, n0 = blockIdx.x * 128;
    const int KB = K2 >> 6;

    const __nv_bfloat16* Ag = A + (long)m0 * K2;
    const __nv_bfloat16* Bg = W + (long)n0 * K2;

    // loader: 1024 16B-chunks per tile, 4 per thread. c -> row=c>>3, chunk j=c&7
    const int lr = tid >> 3, lj = tid & 7;

    auto load_stage = [&](int st, int kb) {
        const __nv_bfloat16* a = Ag + kb * 64;
        const __nv_bfloat16* b = Bg + kb * 64;
        #pragma unroll
        for (int i = 0; i < 4; i++) {
            int r = lr + i * 32;
            uint32_t dsw = r * 128 + ((lj ^ (r & 7)) * 16);
            cp16(sb + SM_A(st) + dsw, a + (long)r * K2 + lj * 8);
        }
        #pragma unroll
        for (int i = 0; i < 4; i++) {
            int r = lr + i * 32;
            uint32_t dsw = r * 128 + ((lj ^ (r & 7)) * 16);
            cp16(sb + SM_B(st) + dsw, b + (long)r * K2 + lj * 8);
        }
        asm volatile("cp.async.commit_group;" ::: "memory");
    };

    float acc[4][4][4];
    #pragma unroll
    for (int i = 0; i < 4; i++)
        #pragma unroll
        for (int j = 0; j < 4; j++)
            #pragma unroll
            for (int e = 0; e < 4; e++) acc[i][j][e] = 0.f;

    load_stage(0, 0);
    load_stage(1, 1);

    for (int kb = 0; kb < KB; kb++) {
        const int st = kb % 3;
        asm volatile("cp.async.wait_group 1;" ::: "memory");
        __syncthreads();
        if (kb + 2 < KB) load_stage((kb + 2) % 3, kb + 2);

        const uint32_t aB = sb + SM_A(st), bB = sb + SM_B(st);
        #pragma unroll
        for (int ks = 0; ks < 4; ks++) {
            const int kk0 = ks * 16;
            uint32_t af[4][4], bf[4][2];
            #pragma unroll
            for (int i = 0; i < 4; i++) {
                int ra = wm * 64 + i * 16 + (lane & 15);
                int kk = kk0 + (lane >> 4) * 8;
                uint32_t ad = aB + ra * 128 + (((kk >> 3) ^ (ra & 7)) * 16);
                ldsm_x4(af[i][0], af[i][1], af[i][2], af[i][3], ad);
            }
            #pragma unroll
            for (int j = 0; j < 4; j++) {
                int rb = wn * 32 + j * 8 + (lane & 7);
                int kk = kk0 + ((lane >> 3) & 1) * 8;
                uint32_t bd = bB + rb * 128 + (((kk >> 3) ^ (rb & 7)) * 16);
                ldsm_x2(bf[j][0], bf[j][1], bd);
            }
            #pragma unroll
            for (int i = 0; i < 4; i++)
                #pragma unroll
                for (int j = 0; j < 4; j++)
                    mma16816(acc[i][j], af[i][0], af[i][1], af[i][2], af[i][3], bf[j][0], bf[j][1]);
        }
    }

    // --- epilogue ---
    const int gr = lane >> 2, gc = (lane & 3) * 2;
    #pragma unroll
    for (int i = 0; i < 4; i++) {
        #pragma unroll
        for (int j = 0; j < 4; j++) {
            int rbase = m0 + wm * 64 + i * 16 + gr;
            int cbase = n0 + wn * 32 + j * 8 + gc;
            #pragma unroll
            for (int e = 0; e < 4; e++) {
                int r = rbase + (e >> 1) * 8;
                int c = cbase + (e & 1);
                float v = acc[i][j][e] * s[c];
                if (HAS_BIAS) v += bias[c];
                if (HAS_RES)  v += res[(long)r * D_MODEL + c];
                long idx;
                if (LAYOUT == 0) {
                    idx = (long)r * ldc + c;
                } else {
                    int b = r >> 10, t = r & 1023, h = c >> 7, d = c & 127;
                    if (LAYOUT == 1) idx = (long)(b * N_HEADS + h) * (TT * DH) + (long)t * DH + d;
                    else             idx = (long)(b * N_HEADS + h) * (TT * DH) + (long)d * TT + t;
                }
                out[idx] = v;
            }
        }
    }
}

// ============================================================================
// GEMM-P: C[M,N] = A_f32[M,K] @ B_f32[N,K]^T   (both split, triple-K)
// EPI: 0 = scores (x 1/sqrt(128)),  1 = P@V (scatter to [b,t,h*128+d])
// (unchanged from round-3 passing version)
// ============================================================================
template<int EPI>
__global__ void __launch_bounds__(256) gemm_p(
    const float* __restrict__ Ab, const float* __restrict__ Bb,
    float* __restrict__ outb, int K, int lda, int ldb, long sAz, long sBz)
{
    constexpr int ST = 56;
    __shared__ __align__(16) __nv_bfloat16 sA[128 * ST];
    __shared__ __align__(16) __nv_bfloat16 sB[128 * ST];

    const int z = blockIdx.z;
    const float* A = Ab + (long)z * sAz;
    const float* B = Bb + (long)z * sBz;

    const int tid = threadIdx.x, lane = tid & 31, w = tid >> 5;
    const int wm = w & 1, wn = w >> 1;
    const int m0 = blockIdx.y * 128, n0 = blockIdx.x * 128;
    const int tg = lane >> 2, tk = (lane & 3) * 2;

    float acc[4][4][4];
    #pragma unroll
    for (int i = 0; i < 4; i++)
        #pragma unroll
        for (int j = 0; j < 4; j++)
            #pragma unroll
            for (int e = 0; e < 4; e++) acc[i][j][e] = 0.f;

    const int la_k = tid & 15, la_r = tid >> 4;

    for (int kb = 0; kb < K; kb += 16) {
        #pragma unroll
        for (int it = 0; it < 8; it++) {
            int r = la_r + it * 16;
            float va = A[(long)(m0 + r) * lda + kb + la_k];
            __nv_bfloat16 hi = __float2bfloat16(va);
            __nv_bfloat16 lo = __float2bfloat16(va - __bfloat162float(hi));
            sA[r * ST + 3 * la_k]     = hi;
            sA[r * ST + 3 * la_k + 1] = lo;
            sA[r * ST + 3 * la_k + 2] = hi;
            float vb = B[(long)(n0 + r) * ldb + kb + la_k];
            hi = __float2bfloat16(vb);
            lo = __float2bfloat16(vb - __bfloat162float(hi));
            sB[r * ST + 3 * la_k]     = hi;
            sB[r * ST + 3 * la_k + 1] = hi;
            sB[r * ST + 3 * la_k + 2] = lo;
        }
        __syncthreads();
        #pragma unroll
        for (int ks = 0; ks < 3; ks++) {
            const int kk0 = ks * 16;
            uint32_t af[4][4], bf[4][2];
            #pragma unroll
            for (int i = 0; i < 4; i++) {
                int ra = wm * 64 + i * 16 + tg;
                af[i][0] = *(const uint32_t*)&sA[(ra    ) * ST + kk0 + tk    ];
                af[i][1] = *(const uint32_t*)&sA[(ra + 8) * ST + kk0 + tk    ];
                af[i][2] = *(const uint32_t*)&sA[(ra    ) * ST + kk0 + tk + 8];
                af[i][3] = *(const uint32_t*)&sA[(ra + 8) * ST + kk0 + tk + 8];
            }
            #pragma unroll
            for (int j = 0; j < 4; j++) {
                int rb = wn * 32 + j * 8 + tg;
                bf[j][0] = *(const uint32_t*)&sB[rb * ST + kk0 + tk    ];
                bf[j][1] = *(const uint32_t*)&sB[rb * ST + kk0 + tk + 8];
            }
            #pragma unroll
            for (int i = 0; i < 4; i++)
                #pragma unroll
                for (int j = 0; j < 4; j++)
                    mma16816(acc[i][j], af[i][0], af[i][1], af[i][2], af[i][3], bf[j][0], bf[j][1]);
        }
        __syncthreads();
    }

    const int gr = tg, gc = tk;
    #pragma unroll
    for (int i = 0; i < 4; i++) {
        #pragma unroll
        for (int j = 0; j < 4; j++) {
            int rbase = m0 + wm * 64 + i * 16 + gr;
            int cbase = n0 + wn * 32 + j * 8 + gc;
            #pragma unroll
            for (int e = 0; e < 4; e++) {
                int r = rbase + (e >> 1) * 8;
                int c = cbase + (e & 1);
                float v = acc[i][j][e];
                if (EPI == 0) {
                    outb[(long)z * TT * TT + (long)r * TT + c] = v * 0.08838834764831845f;
                } else {
                    int b = z >> 4, h = z & 15;
                    outb[((long)(b * TT + r)) * D_MODEL + h * DH + c] = v;
                }
            }
        }
    }
}

// ---------------- reductions ----------------
__device__ __forceinline__ float warp_sum(float v) {
    #pragma unroll
    for (int o = 16; o; o >>= 1) v += __shfl_xor_sync(0xffffffffu, v, o);
    return v;
}
__device__ __forceinline__ float warp_max(float v) {
    #pragma unroll
    for (int o = 16; o; o >>= 1) v = fmaxf(v, __shfl_xor_sync(0xffffffffu, v, o));
    return v;
}
template<int NW>
__device__ __forceinline__ float block_sum(float v, float* buf) {
    int tid = threadIdx.x;
    v = warp_sum(v);
    __syncthreads();
    if ((tid & 31) == 0) buf[tid >> 5] = v;
    __syncthreads();
    if (tid == 0) { float t = 0; for (int i = 0; i < NW; i++) t += buf[i]; buf[0] = t; }
    __syncthreads();
    return buf[0];
}
template<int NW>
__device__ __forceinline__ float block_max(float v, float* buf) {
    int tid = threadIdx.x;
    v = warp_max(v);
    __syncthreads();
    if ((tid & 31) == 0) buf[tid >> 5] = v;
    __syncthreads();
    if (tid == 0) { float t = buf[0]; for (int i = 1; i < NW; i++) t = fmaxf(t, buf[i]); buf[0] = t; }
    __syncthreads();
    return buf[0];
}

// ------- LN (optional) + Hadamard-2048 -> split hi/lo bf16, one block/token -------
template<bool DO_LN>
__global__ void __launch_bounds__(256) ln_had2048(
    const float* __restrict__ in, const float* __restrict__ g,
    const float* __restrict__ bta, __nv_bfloat16* __restrict__ outs)
{
    __shared__ float s[2048];
    __shared__ float red[8];
    const int tid = threadIdx.x;
    const float* x = in + (long)blockIdx.x * 2048;
    float loc[8];
    #pragma unroll
    for (int j = 0; j < 8; j++) loc[j] = x[tid + 256 * j];

    if (DO_LN) {
        float sm = 0.f, sq = 0.f;
        #pragma unroll
        for (int j = 0; j < 8; j++) { sm += loc[j]; sq += loc[j] * loc[j]; }
        float S  = block_sum<8>(sm, red);
        float SQ = block_sum<8>(sq, red);
        float mu = S * (1.0f / 2048.0f);
        float var = SQ * (1.0f / 2048.0f) - mu * mu;
        float inv = rsqrtf(var + 1e-5f);
        #pragma unroll
        for (int j = 0; j < 8; j++) {
            int c = tid + 256 * j;
            loc[j] = (loc[j] - mu) * inv * g[c] + bta[c];
        }
    }
    #pragma unroll
    for (int j = 0; j < 8; j++) s[tid + 256 * j] = loc[j];

    int sh = 0;
    for (int h = 1; h < 2048; h <<= 1, sh++) {
        __syncthreads();
        #pragma unroll
        for (int j = 0; j < 4; j++) {
            int pi = tid + 256 * j;
            int idx = ((pi >> sh) << (sh + 1)) + (pi & (h - 1));
            float a = s[idx], c = s[idx + h];
            s[idx] = a + c;
            s[idx + h] = a - c;
        }
    }
    __syncthreads();
    __nv_bfloat162* o2 = (__nv_bfloat162*)outs + (long)blockIdx.x * 2048;
    #pragma unroll
    for (int j = 0; j < 8; j++) {
        int c = tid + 256 * j;
        float v = s[c] * 0.022097086912079608f;
        __nv_bfloat16 hi = __float2bfloat16(v);
        __nv_bfloat16 lo = __float2bfloat16(v - __bfloat162float(hi));
        o2[c] = __halves2bfloat162(hi, lo);
    }
}

// ------- GELU(exact) + Hadamard-8192 -> split hi/lo bf16, one block/token -------
__global__ void __launch_bounds__(512) gelu_had8192(const float* __restrict__ in, __nv_bfloat16* __restrict__ outs)
{
    __shared__ float s[8192];
    const int tid = threadIdx.x;
    const float* x = in + (long)blockIdx.x * 8192;
    #pragma unroll
    for (int j = 0; j < 16; j++) {
        float v = x[tid + 512 * j];
        v = 0.5f * v * (1.0f + erff(v * 0.7071067811865476f));
        s[tid + 512 * j] = v;
    }
    int sh = 0;
    for (int h = 1; h < 8192; h <<= 1, sh++) {
        __syncthreads();
        #pragma unroll
        for (int j = 0; j < 8; j++) {
            int pi = tid + 512 * j;
            int idx = ((pi >> sh) << (sh + 1)) + (pi & (h - 1));
            float a = s[idx], c = s[idx + h];
            s[idx] = a + c;
            s[idx + h] = a - c;
        }
    }
    __syncthreads();
    __nv_bfloat162* o2 = (__nv_bfloat162*)outs + (long)blockIdx.x * 8192;
    #pragma unroll
    for (int j = 0; j < 16; j++) {
        int c = tid + 512 * j;
        float v = s[c] * 0.011048543456039806f;
        __nv_bfloat16 hi = __float2bfloat16(v);
        __nv_bfloat16 lo = __float2bfloat16(v - __bfloat162float(hi));
        o2[c] = __halves2bfloat162(hi, lo);
    }
}

// ---------------- softmax over rows of 1024 (in-place) ----------------
__global__ void __launch_bounds__(256) softmax1024(float* __restrict__ sc)
{
    __shared__ float red[8];
    const int tid = threadIdx.x;
    float* row = sc + (long)blockIdx.x * 1024;
    float v[4];
    float mx = -3.4e38f;
    #pragma unroll
    for (int j = 0; j < 4; j++) { v[j] = row[tid + 256 * j]; mx = fmaxf(mx, v[j]); }
    float m = block_max<8>(mx, red);
    float sm = 0.f;
    #pragma unroll
    for (int j = 0; j < 4; j++) { v[j] = __expf(v[j] - m); sm += v[j]; }
    float S = block_sum<8>(sm, red);
    float inv = 1.0f / S;
    #pragma unroll
    for (int j = 0; j < 4; j++) row[tid + 256 * j] = v[j] * inv;
}

// ============================================================================
extern "C" void kernel_launch(void* const* d_in, const int* in_sizes, int n_in,
                              void* d_out, int out_size)
{
    const float*  x    = (const float*) d_in[0];
    const float*  ln1g = (const float*) d_in[1];
    const float*  ln1b = (const float*) d_in[2];
    const float*  ln2g = (const float*) d_in[3];
    const float*  ln2b = (const float*) d_in[4];
    const void*   Qq   = d_in[5];
    const float*  sq   = (const float*) d_in[6];
    const void*   Qk   = d_in[7];
    const float*  sk   = (const float*) d_in[8];
    const void*   Qv   = d_in[9];
    const float*  sv   = (const float*) d_in[10];
    const void*   Qo   = d_in[11];
    const float*  so   = (const float*) d_in[12];
    const void*   Qf1  = d_in[13];
    const float*  sf1  = (const float*) d_in[14];
    const float*  bf1  = (const float*) d_in[15];
    const void*   Qf2  = d_in[16];
    const float*  sf2  = (const float*) d_in[17];
    const float*  bf2  = (const float*) d_in[18];
    float* out = (float*)d_out;

    float *q, *k, *vt, *sc, *at, *x1, *ff;
    __nv_bfloat16 *xhs, *ahs, *xh2s, *ffhs, *wb;
    cudaGetSymbolAddress((void**)&q,    g_q);
    cudaGetSymbolAddress((void**)&k,    g_k);
    cudaGetSymbolAddress((void**)&vt,   g_vt);
    cudaGetSymbolAddress((void**)&sc,   g_sc);
    cudaGetSymbolAddress((void**)&at,   g_at);
    cudaGetSymbolAddress((void**)&x1,   g_x1);
    cudaGetSymbolAddress((void**)&ff,   g_ff);
    cudaGetSymbolAddress((void**)&xhs,  g_xhs);
    cudaGetSymbolAddress((void**)&ahs,  g_ahs);
    cudaGetSymbolAddress((void**)&xh2s, g_xh2s);
    cudaGetSymbolAddress((void**)&ffhs, g_ffhs);
    cudaGetSymbolAddress((void**)&wb,   g_wb);

    __nv_bfloat16* wq  = wb;
    __nv_bfloat16* wk  = wb + NWD2;
    __nv_bfloat16* wv  = wb + 2 * NWD2;
    __nv_bfloat16* wo  = wb + 3 * NWD2;
    __nv_bfloat16* wf1 = wb + 4 * NWD2;
    __nv_bfloat16* wf2 = wb + 4 * NWD2 + NWF2;

    cudaFuncSetAttribute((const void*)gemm_w2<1, false, false>, cudaFuncAttributeMaxDynamicSharedMemorySize, SMEM_W);
    cudaFuncSetAttribute((const void*)gemm_w2<2, false, false>, cudaFuncAttributeMaxDynamicSharedMemorySize, SMEM_W);
    cudaFuncSetAttribute((const void*)gemm_w2<0, false, true>,  cudaFuncAttributeMaxDynamicSharedMemorySize, SMEM_W);
    cudaFuncSetAttribute((const void*)gemm_w2<0, true, false>,  cudaFuncAttributeMaxDynamicSharedMemorySize, SMEM_W);
    cudaFuncSetAttribute((const void*)gemm_w2<0, true, true>,   cudaFuncAttributeMaxDynamicSharedMemorySize, SMEM_W);

    const long NWD = (long)D_MODEL * D_MODEL;
    const long NWF = (long)D_FF * D_MODEL;

    // 0. dtype probe + normalize weights to K-duplicated bf16
    zero_counters<<<1, 1>>>();
    probe_dtype<<<4096, 256>>>(Qq, 1 << 20);
    convert_w<<<(int)((NWD + 255) / 256), 256>>>(Qq,  wq,  NWD);
    convert_w<<<(int)((NWD + 255) / 256), 256>>>(Qk,  wk,  NWD);
    convert_w<<<(int)((NWD + 255) / 256), 256>>>(Qv,  wv,  NWD);
    convert_w<<<(int)((NWD + 255) / 256), 256>>>(Qo,  wo,  NWD);
    convert_w<<<(int)((NWF + 255) / 256), 256>>>(Qf1, wf1, NWF);
    convert_w<<<(int)((NWF + 255) / 256), 256>>>(Qf2, wf2, NWF);

    // 1. LN1 + Hadamard -> split
    ln_had2048<true><<<BT, 256>>>(x, ln1g, ln1b, xhs);
    // 2-4. Q/K/V projections
    gemm_w2<1, false, false><<<dim3(16, 32), 256, SMEM_W>>>(xhs, wq, 2 * D_MODEL, sq, nullptr, nullptr, q,  0);
    gemm_w2<1, false, false><<<dim3(16, 32), 256, SMEM_W>>>(xhs, wk, 2 * D_MODEL, sk, nullptr, nullptr, k,  0);
    gemm_w2<2, false, false><<<dim3(16, 32), 256, SMEM_W>>>(xhs, wv, 2 * D_MODEL, sv, nullptr, nullptr, vt, 0);
    // 5. scores = q @ k^T / sqrt(128)
    gemm_p<0><<<dim3(8, 8, BH), 256>>>(q, k, sc, DH, DH, DH, (long)TT * DH, (long)TT * DH);
    // 6. softmax
    softmax1024<<<BH * TT, 256>>>(sc);
    // 7. attn = P @ V
    gemm_p<1><<<dim3(1, 8, BH), 256>>>(sc, vt, at, TT, TT, TT, (long)TT * TT, (long)DH * TT);
    // 8. Hadamard(attn) -> split
    ln_had2048<false><<<BT, 256>>>(at, nullptr, nullptr, ahs);
    // 9. x1 = x + O-proj
    gemm_w2<0, false, true><<<dim3(16, 32), 256, SMEM_W>>>(ahs, wo, 2 * D_MODEL, so, nullptr, x, x1, D_MODEL);
    // 10. LN2 + Hadamard -> split
    ln_had2048<true><<<BT, 256>>>(x1, ln2g, ln2b, xh2s);
    // 11. FF1 (+bias)
    gemm_w2<0, true, false><<<dim3(64, 32), 256, SMEM_W>>>(xh2s, wf1, 2 * D_MODEL, sf1, bf1, nullptr, ff, D_FF);
    // 12. GELU + Hadamard-8192 -> split
    gelu_had8192<<<BT, 512>>>(ff, ffhs);
    // 13. out = x1 + FF2 (+bias)
    gemm_w2<0, true, true><<<dim3(16, 32), 256, SMEM_W>>>(ffhs, wf2, 2 * D_FF, sf2, bf2, x1, out, D_MODEL);
}